// round 3
// baseline (speedup 1.0000x reference)
#include <cuda_runtime.h>

#define NTHREADS 128

// Broadcast one fp32 into a packed f32x2 register pair.
static __device__ __forceinline__ unsigned long long bcast2(float x)
{
    unsigned long long r;
    unsigned u = __float_as_uint(x);
    asm("mov.b64 %0, {%1, %1};" : "=l"(r) : "r"(u));
    return r;
}

// One tap: 4 positions x 32 outputs (16 packed f32x2 each).
// wrow -> w[k][half*32 .. +31] in SMEM (128B aligned). All acc indices constant.
static __device__ __forceinline__ void tap4(unsigned long long* __restrict__ acc,
                                            const float* __restrict__ wrow,
                                            float xv0, float xv1, float xv2, float xv3)
{
    unsigned long long xx0 = bcast2(xv0), xx1 = bcast2(xv1);
    unsigned long long xx2 = bcast2(xv2), xx3 = bcast2(xv3);
    const ulonglong2* wq = reinterpret_cast<const ulonglong2*>(wrow);
#pragma unroll
    for (int q = 0; q < 8; ++q) {
        ulonglong2 wv = wq[q];
        asm("fma.rn.f32x2 %0, %1, %2, %0;" : "+l"(acc[0 * 16 + 2 * q])     : "l"(xx0), "l"(wv.x));
        asm("fma.rn.f32x2 %0, %1, %2, %0;" : "+l"(acc[0 * 16 + 2 * q + 1]) : "l"(xx0), "l"(wv.y));
        asm("fma.rn.f32x2 %0, %1, %2, %0;" : "+l"(acc[1 * 16 + 2 * q])     : "l"(xx1), "l"(wv.x));
        asm("fma.rn.f32x2 %0, %1, %2, %0;" : "+l"(acc[1 * 16 + 2 * q + 1]) : "l"(xx1), "l"(wv.y));
        asm("fma.rn.f32x2 %0, %1, %2, %0;" : "+l"(acc[2 * 16 + 2 * q])     : "l"(xx2), "l"(wv.x));
        asm("fma.rn.f32x2 %0, %1, %2, %0;" : "+l"(acc[2 * 16 + 2 * q + 1]) : "l"(xx2), "l"(wv.y));
        asm("fma.rn.f32x2 %0, %1, %2, %0;" : "+l"(acc[3 * 16 + 2 * q])     : "l"(xx3), "l"(wv.x));
        asm("fma.rn.f32x2 %0, %1, %2, %0;" : "+l"(acc[3 * 16 + 2 * q + 1]) : "l"(xx3), "l"(wv.y));
    }
}

// Epilogue for ONE position, constant-indexed accumulator slice.
// relu -> half-softmax -> shfl-combine -> scale -> pixel-shuffled store.
static __device__ __forceinline__ void finish_pos(float* __restrict__ out,
                                                  const unsigned long long* __restrict__ a,
                                                  float xsel, int n, int gi, int gj,
                                                  int half)
{
    float v[32];
#pragma unroll
    for (int q = 0; q < 16; ++q) {
        unsigned lo, hi;
        asm("mov.b64 {%0, %1}, %2;" : "=r"(lo), "=r"(hi) : "l"(a[q]));
        v[2 * q]     = fmaxf(__uint_as_float(lo), 0.0f);
        v[2 * q + 1] = fmaxf(__uint_as_float(hi), 0.0f);
    }
    float m = v[0];
#pragma unroll
    for (int o = 1; o < 32; ++o) m = fmaxf(m, v[o]);
    float s = 0.0f;
#pragma unroll
    for (int o = 0; o < 32; ++o) {
        v[o] = __expf(v[o] - m);
        s += v[o];
    }
    float pm = __shfl_xor_sync(0xffffffffu, m, 16);
    float ps = __shfl_xor_sync(0xffffffffu, s, 16);
    float M  = fmaxf(m, pm);
    float S  = s * __expf(m - M) + ps * __expf(pm - M);
    float scale = xsel * __expf(m - M) / S;

    float* base = out + ((size_t)n << 18)
                      + (size_t)(gi * 8 + half * 4) * 512 + gj * 8;
#pragma unroll
    for (int a2 = 0; a2 < 4; ++a2) {
        float4 t0 = make_float4(scale * v[a2 * 8 + 0], scale * v[a2 * 8 + 1],
                                scale * v[a2 * 8 + 2], scale * v[a2 * 8 + 3]);
        float4 t1 = make_float4(scale * v[a2 * 8 + 4], scale * v[a2 * 8 + 5],
                                scale * v[a2 * 8 + 6], scale * v[a2 * 8 + 7]);
        *reinterpret_cast<float4*>(base + (size_t)a2 * 512)     = t0;
        *reinterpret_cast<float4*>(base + (size_t)a2 * 512 + 4) = t1;
    }
}

// ---------------------------------------------------------------------------
// One CTA = one batch, one 16x16 tile of low-res positions.
// 128 threads: half = lane>>4 selects outputs [0,32) or [32,64);
// group g = warp*16 + (lane&15): col j = g&15, rows r0..r0+3 with r0=4*(g>>4).
// ---------------------------------------------------------------------------
__global__ void __launch_bounds__(NTHREADS, 3)
sr_kernel(const float* __restrict__ gx0, const float* __restrict__ gx1,
          const float* __restrict__ gx2, const float* __restrict__ gw,
          float* __restrict__ out)
{
    extern __shared__ float sm[];
    float* s_w  = sm;              // 189*64 = 12096 floats
    float* s_x0 = s_w + 12096;     // 18*18  = 324
    float* s_x1 = s_x0 + 324;      // 36*36  = 1296
    float* s_x2 = s_x1 + 1296;     // 72*72  = 5184   (total 75600 B)

    const int tid  = threadIdx.x;
    const int n    = blockIdx.z;
    const int i0   = blockIdx.y * 16;
    const int j0   = blockIdx.x * 16;
    const int lane = tid & 31;
    const int warp = tid >> 5;
    const int half = lane >> 4;                 // output half
    const int g    = warp * 16 + (lane & 15);   // position group 0..63
    const int j    = g & 15;                    // tile col
    const int r0   = (g >> 4) * 4;              // first of 4 tile rows

    // --- stage weights ---
    {
        const float4* wg = reinterpret_cast<const float4*>(gw);
        float4* ws = reinterpret_cast<float4*>(s_w);
        for (int idx = tid; idx < 3024; idx += NTHREADS) ws[idx] = wg[idx];
    }
    // --- stage x0 patch ---
    {
        const float* src = gx0 + n * 4096;
        for (int idx = tid; idx < 18 * 18; idx += NTHREADS) {
            int r = idx / 18, c = idx - r * 18;
            int gi = i0 - 1 + r, gj = j0 - 1 + c;
            float v = 0.0f;
            if ((unsigned)gi < 64u && (unsigned)gj < 64u) v = src[gi * 64 + gj];
            s_x0[idx] = v;
        }
    }
    // --- stage x1 patch ---
    {
        const float* src = gx1 + n * 16384;
        for (int idx = tid; idx < 36 * 36; idx += NTHREADS) {
            int r = idx / 36, c = idx - r * 36;
            int gi = 2 * i0 - 2 + r, gj = 2 * j0 - 2 + c;
            float v = 0.0f;
            if ((unsigned)gi < 128u && (unsigned)gj < 128u) v = src[gi * 128 + gj];
            s_x1[idx] = v;
        }
    }
    // --- stage x2 patch ---
    {
        const float* src = gx2 + n * 65536;
        for (int idx = tid; idx < 72 * 72; idx += NTHREADS) {
            int r = idx / 72, c = idx - r * 72;
            int gi = 4 * i0 - 4 + r, gj = 4 * j0 - 4 + c;
            float v = 0.0f;
            if ((unsigned)gi < 256u && (unsigned)gj < 256u) v = src[gi * 256 + gj];
            s_x2[idx] = v;
        }
    }
    __syncthreads();

    unsigned long long acc[64];
#pragma unroll
    for (int q = 0; q < 64; ++q) acc[q] = 0ull;

    const float* wk = s_w + half * 32;

    // layer 0: 3x3 taps; x0 row for pos p (p = r0+pp): (p+di)*18 + j + dj
#pragma unroll 1
    for (int di = 0; di < 3; ++di) {
        const float* xr = s_x0 + (r0 + di) * 18 + j;
#pragma unroll
        for (int dj = 0; dj < 3; ++dj) {
            tap4(acc, wk, xr[0 * 18 + dj], xr[1 * 18 + dj],
                          xr[2 * 18 + dj], xr[3 * 18 + dj]);
            wk += 64;
        }
    }
    // layer 1: 6x6 taps; row (2p+di)*36 + 2j + dj, pos stride = 2 rows (72 floats)
#pragma unroll 1
    for (int di = 0; di < 6; ++di) {
        const float* xr = s_x1 + (2 * r0 + di) * 36 + 2 * j;
#pragma unroll
        for (int dj = 0; dj < 6; ++dj) {
            tap4(acc, wk, xr[0 * 72 + dj], xr[1 * 72 + dj],
                          xr[2 * 72 + dj], xr[3 * 72 + dj]);
            wk += 64;
        }
    }
    // layer 2: 12x12 taps; row (4p+di)*72 + 4j + dj, pos stride = 4 rows (288 floats)
#pragma unroll 1
    for (int di = 0; di < 12; ++di) {
        const float* xr = s_x2 + (4 * r0 + di) * 72 + 4 * j;
#pragma unroll
        for (int dj = 0; dj < 12; ++dj) {
            tap4(acc, wk, xr[0 * 288 + dj], xr[1 * 288 + dj],
                          xr[2 * 288 + dj], xr[3 * 288 + dj]);
            wk += 64;
        }
    }

    // --- epilogue: constant-indexed per position (no dynamic acc indexing!) ---
    const float xs0 = s_x0[(r0 + 1) * 18 + (j + 1)];
    const float xs1 = s_x0[(r0 + 2) * 18 + (j + 1)];
    const float xs2 = s_x0[(r0 + 3) * 18 + (j + 1)];
    const float xs3 = s_x0[(r0 + 4) * 18 + (j + 1)];

    finish_pos(out, acc +  0, xs0, n, i0 + r0 + 0, j0 + j, half);
    finish_pos(out, acc + 16, xs1, n, i0 + r0 + 1, j0 + j, half);
    finish_pos(out, acc + 32, xs2, n, i0 + r0 + 2, j0 + j, half);
    finish_pos(out, acc + 48, xs3, n, i0 + r0 + 3, j0 + j, half);
}

extern "C" void kernel_launch(void* const* d_in, const int* in_sizes, int n_in,
                              void* d_out, int out_size)
{
    const float* x0 = (const float*)d_in[0];
    const float* x1 = (const float*)d_in[1];
    const float* x2 = (const float*)d_in[2];
    const float* w  = (const float*)d_in[3];
    float* out = (float*)d_out;

    const int smem_bytes = 18900 * (int)sizeof(float);
    cudaFuncSetAttribute(sr_kernel, cudaFuncAttributeMaxDynamicSharedMemorySize,
                         smem_bytes);

    dim3 grid(4, 4, 64);
    sr_kernel<<<grid, NTHREADS, smem_bytes>>>(x0, x1, x2, w, out);
}

// round 5
// speedup vs baseline: 2.1290x; 2.1290x over previous
#include <cuda_runtime.h>
#include <cstdint>

#define NT 256

// SMEM layout (floats). Stride 196: bank = (196*row + k) % 32 = (4*row + k) % 32
// -> A/B fragment loads (row=lane>>2, k=k0+(lane&3)) are conflict-free.
#define XSTR 196
#define NF_X (128 * XSTR)          // 25088 f
#define NF_W (64 * XSTR)           // 12544 f
#define OFF_X 0
#define OFF_W (OFF_X + NF_X)
#define OFF_P0 (OFF_W + NF_W)      // x0 patch 10x18  = 180 f
#define OFF_P1 (OFF_P0 + 180)      // x1 patch 20x36  = 720 f
#define OFF_P2 (OFF_P1 + 720)      // x2 patch 40x72  = 2880 f
#define NF_TOTAL (OFF_P2 + 2880)   // 41412 f = 165648 B

static __device__ __forceinline__ uint32_t f2tf32(float x) {
    uint32_t r;
    asm("cvt.rna.tf32.f32 %0, %1;" : "=r"(r) : "f"(x));
    return r;
}

static __device__ __forceinline__ void mma_tf32(float* c,
                                                uint32_t a0, uint32_t a1,
                                                uint32_t a2, uint32_t a3,
                                                uint32_t b0, uint32_t b1)
{
    asm volatile(
        "mma.sync.aligned.m16n8k8.row.col.f32.tf32.tf32.f32 "
        "{%0,%1,%2,%3}, {%4,%5,%6,%7}, {%8,%9}, {%0,%1,%2,%3};"
        : "+f"(c[0]), "+f"(c[1]), "+f"(c[2]), "+f"(c[3])
        : "r"(a0), "r"(a1), "r"(a2), "r"(a3), "r"(b0), "r"(b1));
}

// ---------------------------------------------------------------------------
// CTA: batch n, 8x16 tile of low-res positions (M=128), K=192 (189+pad), N=64.
// K order: layer2 k=12*di+dj [0,144), layer1 144+6*di+dj, layer0 180+3*di+dj,
// pad 189..191 (zeros). Warp w computes rows m0=16w..m0+15 x all 64 outputs.
// ---------------------------------------------------------------------------
__global__ void __launch_bounds__(NT, 1)
sr_mma(const float* __restrict__ gx0, const float* __restrict__ gx1,
       const float* __restrict__ gx2, const float* __restrict__ gw,
       float* __restrict__ out)
{
    extern __shared__ float sm[];
    float* s_x0 = sm + OFF_P0;
    float* s_x1 = sm + OFF_P1;
    float* s_x2 = sm + OFF_P2;

    const int tid  = threadIdx.x;
    const int wid  = tid >> 5;
    const int lane = tid & 31;
    const int n    = blockIdx.z;
    const int i0   = blockIdx.y * 8;
    const int j0   = blockIdx.x * 16;

    // ---- stage patches (raw fp32) ----
    {
        const float* src = gx0 + n * 4096;
        for (int idx = tid; idx < 10 * 18; idx += NT) {
            int r = idx / 18, c = idx - r * 18;
            int gi = i0 - 1 + r, gj = j0 - 1 + c;
            float v = 0.0f;
            if ((unsigned)gi < 64u && (unsigned)gj < 64u) v = src[gi * 64 + gj];
            s_x0[idx] = v;
        }
    }
    {
        const float* src = gx1 + n * 16384;
        for (int idx = tid; idx < 20 * 36; idx += NT) {
            int r = idx / 36, c = idx - r * 36;
            int gi = 2 * i0 - 2 + r, gj = 2 * j0 - 2 + c;
            float v = 0.0f;
            if ((unsigned)gi < 128u && (unsigned)gj < 128u) v = src[gi * 128 + gj];
            s_x1[idx] = v;
        }
    }
    {
        const float* src = gx2 + n * 65536;
        for (int idx = tid; idx < 40 * 72; idx += NT) {
            int r = idx / 72, c = idx - r * 72;
            int gi = 4 * i0 - 4 + r, gj = 4 * j0 - 4 + c;
            float v = 0.0f;
            if ((unsigned)gi < 256u && (unsigned)gj < 256u) v = src[gi * 256 + gj];
            s_x2[idx] = v;
        }
    }
    // ---- stage W as sW[n][k] (transpose + K-permute + tf32 round) ----
    {
        uint32_t* sw = (uint32_t*)(sm + OFF_W);
        for (int e = tid; e < 12096; e += NT) {
            int kk = e >> 6, nn = e & 63;
            int k = (kk < 9) ? (180 + kk) : (kk < 45) ? (144 + kk - 9) : (kk - 45);
            sw[nn * XSTR + k] = f2tf32(gw[e]);
        }
        if (tid < 192) {                       // zero pad taps k=189..191
            int nn = tid & 63, k = 189 + (tid >> 6);
            sw[nn * XSTR + k] = 0u;
        }
    }
    __syncthreads();

    // ---- build X rows (tf32-rounded). p = tid>>1 builds row p; h splits work.
    {
        const int p = tid >> 1, h = tid & 1;
        const int r = p >> 4, c = p & 15;
        uint32_t* Xr = (uint32_t*)(sm + OFF_X) + p * XSTR;
        const int dlo = h ? 8 : 0, dhi = h ? 12 : 8;
        // layer2: k = 12*di + dj
        for (int di = dlo; di < dhi; ++di) {
            const float4* src = (const float4*)(s_x2 + (4 * r + di) * 72 + 4 * c);
#pragma unroll
            for (int q = 0; q < 3; ++q) {
                float4 v = src[q];
                uint4 u = make_uint4(f2tf32(v.x), f2tf32(v.y), f2tf32(v.z), f2tf32(v.w));
                *(uint4*)(Xr + 12 * di + 4 * q) = u;
            }
        }
        if (h) {
            // layer1: k = 144 + 6*di + dj
#pragma unroll
            for (int di = 0; di < 6; ++di) {
                const float* src = s_x1 + (2 * r + di) * 36 + 2 * c;
#pragma unroll
                for (int dj = 0; dj < 6; ++dj)
                    Xr[144 + 6 * di + dj] = f2tf32(src[dj]);
            }
            // layer0: k = 180 + 3*di + dj
#pragma unroll
            for (int di = 0; di < 3; ++di) {
                const float* src = s_x0 + (r + di) * 18 + c;
#pragma unroll
                for (int dj = 0; dj < 3; ++dj)
                    Xr[180 + 3 * di + dj] = f2tf32(src[dj]);
            }
            Xr[189] = 0u; Xr[190] = 0u; Xr[191] = 0u;
        }
    }
    __syncthreads();

    // ---- GEMM: warp slab m0..m0+15 x 64, 24 K-steps of m16n8k8 ----
    const int g = lane >> 2, t = lane & 3;
    const int m0 = wid * 16;
    const uint32_t* Ar = (const uint32_t*)(sm + OFF_X) + (m0 + g) * XSTR + t;
    const uint32_t* Br = (const uint32_t*)(sm + OFF_W) + g * XSTR + t;

    float acc[8][4];
#pragma unroll
    for (int nb = 0; nb < 8; ++nb)
#pragma unroll
        for (int q = 0; q < 4; ++q) acc[nb][q] = 0.0f;

#pragma unroll 2
    for (int s = 0; s < 24; ++s) {
        const int k0 = 8 * s;
        uint32_t a0 = Ar[k0];
        uint32_t a1 = Ar[8 * XSTR + k0];
        uint32_t a2 = Ar[k0 + 4];
        uint32_t a3 = Ar[8 * XSTR + k0 + 4];
#pragma unroll
        for (int nb = 0; nb < 8; ++nb) {
            uint32_t b0 = Br[nb * 8 * XSTR + k0];
            uint32_t b1 = Br[nb * 8 * XSTR + k0 + 4];
            mma_tf32(acc[nb], a0, a1, a2, a3, b0, b1);
        }
    }

    // ---- epilogue: two position rows per thread (p0 = m0+g, p1 = p0+8) ----
#pragma unroll
    for (int rr = 0; rr < 2; ++rr) {
        float v[16];
#pragma unroll
        for (int nb = 0; nb < 8; ++nb) {
            v[2 * nb]     = fmaxf(acc[nb][rr * 2],     0.0f);
            v[2 * nb + 1] = fmaxf(acc[nb][rr * 2 + 1], 0.0f);
        }
        float m = v[0];
#pragma unroll
        for (int o = 1; o < 16; ++o) m = fmaxf(m, v[o]);
        m = fmaxf(m, __shfl_xor_sync(0xffffffffu, m, 1));
        m = fmaxf(m, __shfl_xor_sync(0xffffffffu, m, 2));
        float ssum = 0.0f;
#pragma unroll
        for (int o = 0; o < 16; ++o) {
            v[o] = __expf(v[o] - m);
            ssum += v[o];
        }
        ssum += __shfl_xor_sync(0xffffffffu, ssum, 1);
        ssum += __shfl_xor_sync(0xffffffffu, ssum, 2);

        const int c   = g + rr * 8;           // tile col 0..15
        const int r   = wid;                  // tile row
        const float xsel  = s_x0[(r + 1) * 18 + (c + 1)];
        const float scale = xsel / ssum;

        const int gi = i0 + r, gj = j0 + c;
        float* base = out + ((size_t)n << 18) + (size_t)(gi * 8) * 512 + gj * 8 + 2 * t;
#pragma unroll
        for (int nb = 0; nb < 8; ++nb) {
            float2 o2 = make_float2(scale * v[2 * nb], scale * v[2 * nb + 1]);
            *(float2*)(base + (size_t)nb * 512) = o2;
        }
    }
}

extern "C" void kernel_launch(void* const* d_in, const int* in_sizes, int n_in,
                              void* d_out, int out_size)
{
    const float* x0 = (const float*)d_in[0];
    const float* x1 = (const float*)d_in[1];
    const float* x2 = (const float*)d_in[2];
    const float* w  = (const float*)d_in[3];
    float* out = (float*)d_out;

    const int smem_bytes = NF_TOTAL * (int)sizeof(float);   // 165648 B
    cudaFuncSetAttribute(sr_mma, cudaFuncAttributeMaxDynamicSharedMemorySize,
                         smem_bytes);

    dim3 grid(4, 8, 64);   // (j-tiles, i-tiles, batch) -> 2048 CTAs
    sr_mma<<<grid, NT, smem_bytes>>>(x0, x1, x2, w, out);
}

// round 6
// speedup vs baseline: 4.8878x; 2.2958x over previous
#include <cuda_runtime.h>
#include <cstdint>

#define NT 256
#define XSTR 196                    // W row stride (floats): banks = 4n + k mod 32

// SMEM layout (floats)
#define OFF_W   0                   // W: 64 x 196 = 12544 f (tf32 bits)
#define OFF_P0  12544               // x0 patch 10x18 = 180 f
#define OFF_P1  (OFF_P0 + 180)      // x1 patch 20x36 = 720 f
#define OFF_P2  (OFF_P1 + 720)      // x2 patch 40x72 = 2880 f
#define NF_TOTAL (OFF_P2 + 2880)    // 16324 f = 65296 B  -> 3 CTAs/SM

static __device__ __forceinline__ uint32_t f2tf32(float x) {
    uint32_t r;
    asm("cvt.rna.tf32.f32 %0, %1;" : "=r"(r) : "f"(x));
    return r;
}

static __device__ __forceinline__ void mma_tf32(float* c,
                                                uint32_t a0, uint32_t a1,
                                                uint32_t a2, uint32_t a3,
                                                uint32_t b0, uint32_t b1)
{
    asm volatile(
        "mma.sync.aligned.m16n8k8.row.col.f32.tf32.tf32.f32 "
        "{%0,%1,%2,%3}, {%4,%5,%6,%7}, {%8,%9}, {%0,%1,%2,%3};"
        : "+f"(c[0]), "+f"(c[1]), "+f"(c[2]), "+f"(c[3])
        : "r"(a0), "r"(a1), "r"(a2), "r"(a3), "r"(b0), "r"(b1));
}

// Patch element for logical (tile-row r, tile-col c, k). k is a compile-time
// constant after unrolling, so the divisions fold to immediate offsets.
// K order: layer2 k=12*di+dj in [0,144); layer1 144+6*di+dj; layer0 180+3*di+dj;
// k>=189 pad (zero).
static __device__ __forceinline__ float ldx(const float* __restrict__ s0,
                                            const float* __restrict__ s1,
                                            const float* __restrict__ s2,
                                            int r, int c, int k)
{
    if (k < 144)      return s2[(4 * r + k / 12) * 72 + 4 * c + (k % 12)];
    else if (k < 180) { int u = k - 144; return s1[(2 * r + u / 6) * 36 + 2 * c + (u % 6)]; }
    else if (k < 189) { int u = k - 180; return s0[(r + u / 3) * 18 + c + (u % 3)]; }
    else              return 0.0f;
}

// ---------------------------------------------------------------------------
// CTA: batch n, 8x16 position tile (M=128), K=192, N=64.
// Warp w owns tile row r=w (16 positions) x all 64 outputs.
// A fragments load straight from patch SMEM (no X tile).
// ---------------------------------------------------------------------------
__global__ void __launch_bounds__(NT, 3)
sr_mma(const float* __restrict__ gx0, const float* __restrict__ gx1,
       const float* __restrict__ gx2, const float* __restrict__ gw,
       float* __restrict__ out)
{
    extern __shared__ float sm[];
    float* s_x0 = sm + OFF_P0;
    float* s_x1 = sm + OFF_P1;
    float* s_x2 = sm + OFF_P2;

    const int tid  = threadIdx.x;
    const int wid  = tid >> 5;
    const int lane = tid & 31;
    const int n    = blockIdx.z;
    const int i0   = blockIdx.y * 8;
    const int j0   = blockIdx.x * 16;

    // ---- stage patches ----
    {
        const float* src = gx0 + n * 4096;
        for (int idx = tid; idx < 10 * 18; idx += NT) {
            int r = idx / 18, c = idx - r * 18;
            int gi = i0 - 1 + r, gj = j0 - 1 + c;
            float v = 0.0f;
            if ((unsigned)gi < 64u && (unsigned)gj < 64u) v = src[gi * 64 + gj];
            s_x0[idx] = v;
        }
    }
    {
        const float* src = gx1 + n * 16384;
        for (int idx = tid; idx < 20 * 36; idx += NT) {
            int r = idx / 36, c = idx - r * 36;
            int gi = 2 * i0 - 2 + r, gj = 2 * j0 - 2 + c;
            float v = 0.0f;
            if ((unsigned)gi < 128u && (unsigned)gj < 128u) v = src[gi * 128 + gj];
            s_x1[idx] = v;
        }
    }
    {
        const float* src = gx2 + n * 65536;
        for (int idx = tid; idx < 40 * 72; idx += NT) {
            int r = idx / 72, c = idx - r * 72;
            int gi = 4 * i0 - 4 + r, gj = 4 * j0 - 4 + c;
            float v = 0.0f;
            if ((unsigned)gi < 256u && (unsigned)gj < 256u) v = src[gi * 256 + gj];
            s_x2[idx] = v;
        }
    }
    // ---- stage W as sW[n][k] (transpose + K-permute + tf32 round) ----
    {
        uint32_t* sw = (uint32_t*)(sm + OFF_W);
        for (int e = tid; e < 12096; e += NT) {
            int kk = e >> 6, nn = e & 63;
            int k = (kk < 9) ? (180 + kk) : (kk < 45) ? (144 + kk - 9) : (kk - 45);
            sw[nn * XSTR + k] = f2tf32(gw[e]);
        }
        if (tid < 192) {                       // pad taps k=189..191
            int nn = tid & 63, k = 189 + (tid >> 6);
            sw[nn * XSTR + k] = 0u;
        }
    }
    __syncthreads();

    // ---- GEMM: 24 K-steps of m16n8k8, A from patches, B from sW ----
    const int g = lane >> 2, t = lane & 3;
    const int r = wid;                 // tile row for this warp
    const int c0 = g, c1 = g + 8;      // the two position columns of this thread
    const uint32_t* Br = (const uint32_t*)(sm + OFF_W) + g * XSTR + t;

    float acc[8][4];
#pragma unroll
    for (int nb = 0; nb < 8; ++nb)
#pragma unroll
        for (int q = 0; q < 4; ++q) acc[nb][q] = 0.0f;

#pragma unroll
    for (int s = 0; s < 24; ++s) {
        const int k0 = 8 * s;
        uint32_t a0 = f2tf32(ldx(s_x0, s_x1, s_x2, r, c0, k0 + t));
        uint32_t a1 = f2tf32(ldx(s_x0, s_x1, s_x2, r, c1, k0 + t));
        uint32_t a2 = f2tf32(ldx(s_x0, s_x1, s_x2, r, c0, k0 + 4 + t));
        uint32_t a3 = f2tf32(ldx(s_x0, s_x1, s_x2, r, c1, k0 + 4 + t));
#pragma unroll
        for (int nb = 0; nb < 8; ++nb) {
            uint32_t b0 = Br[nb * 8 * XSTR + k0];
            uint32_t b1 = Br[nb * 8 * XSTR + k0 + 4];
            mma_tf32(acc[nb], a0, a1, a2, a3, b0, b1);
        }
    }

    // ---- epilogue: two position rows per thread (cols c0, c1) ----
#pragma unroll
    for (int rr = 0; rr < 2; ++rr) {
        float v[16];
#pragma unroll
        for (int nb = 0; nb < 8; ++nb) {
            v[2 * nb]     = fmaxf(acc[nb][rr * 2],     0.0f);
            v[2 * nb + 1] = fmaxf(acc[nb][rr * 2 + 1], 0.0f);
        }
        float m = v[0];
#pragma unroll
        for (int o = 1; o < 16; ++o) m = fmaxf(m, v[o]);
        m = fmaxf(m, __shfl_xor_sync(0xffffffffu, m, 1));
        m = fmaxf(m, __shfl_xor_sync(0xffffffffu, m, 2));
        float ssum = 0.0f;
#pragma unroll
        for (int o = 0; o < 16; ++o) {
            v[o] = __expf(v[o] - m);
            ssum += v[o];
        }
        ssum += __shfl_xor_sync(0xffffffffu, ssum, 1);
        ssum += __shfl_xor_sync(0xffffffffu, ssum, 2);

        const int c = (rr == 0) ? c0 : c1;
        const float xsel  = s_x0[(r + 1) * 18 + (c + 1)];
        const float scale = xsel / ssum;

        const int gi = i0 + r, gj = j0 + c;
        float* base = out + ((size_t)n << 18) + (size_t)(gi * 8) * 512 + gj * 8 + 2 * t;
#pragma unroll
        for (int nb = 0; nb < 8; ++nb) {
            float2 o2 = make_float2(scale * v[2 * nb], scale * v[2 * nb + 1]);
            *(float2*)(base + (size_t)nb * 512) = o2;
        }
    }
}

extern "C" void kernel_launch(void* const* d_in, const int* in_sizes, int n_in,
                              void* d_out, int out_size)
{
    const float* x0 = (const float*)d_in[0];
    const float* x1 = (const float*)d_in[1];
    const float* x2 = (const float*)d_in[2];
    const float* w  = (const float*)d_in[3];
    float* out = (float*)d_out;

    const int smem_bytes = NF_TOTAL * (int)sizeof(float);   // 65296 B
    cudaFuncSetAttribute(sr_mma, cudaFuncAttributeMaxDynamicSharedMemorySize,
                         smem_bytes);

    dim3 grid(4, 8, 64);   // 2048 CTAs
    sr_mma<<<grid, NT, smem_bytes>>>(x0, x1, x2, w, out);
}

// round 7
// speedup vs baseline: 5.8856x; 1.2042x over previous
#include <cuda_runtime.h>
#include <cstdint>

#define NT 256
#define XSTR 196                    // W row stride (floats): banks = 4n + k mod 32

// SMEM layout (32-bit words)
#define OFF_W   0                   // W: 64 x 196 tf32 bits = 12544
#define OFF_P0  12544               // x0 patch 18x18 fp32 = 324
#define OFF_P1  (OFF_P0 + 324)      // x1 patch 36x36 tf32 = 1296
#define OFF_P2  (OFF_P1 + 1296)     // x2 patch 72x72 tf32 = 5184
#define NW_TOTAL (OFF_P2 + 5184)    // 19348 w = 77392 B -> 2 CTAs/SM

static __device__ __forceinline__ uint32_t f2tf32(float x) {
    uint32_t r;
    asm("cvt.rna.tf32.f32 %0, %1;" : "=r"(r) : "f"(x));
    return r;
}

static __device__ __forceinline__ void mma_tf32(float* c,
                                                uint32_t a0, uint32_t a1,
                                                uint32_t a2, uint32_t a3,
                                                uint32_t b0, uint32_t b1)
{
    asm volatile(
        "mma.sync.aligned.m16n8k8.row.col.f32.tf32.tf32.f32 "
        "{%0,%1,%2,%3}, {%4,%5,%6,%7}, {%8,%9}, {%0,%1,%2,%3};"
        : "+f"(c[0]), "+f"(c[1]), "+f"(c[2]), "+f"(c[3])
        : "r"(a0), "r"(a1), "r"(a2), "r"(a3), "r"(b0), "r"(b1));
}

// A element for (tile-row r, tile-col c, k); k compile-time constant after
// unroll -> immediate offsets. Layers 1/2 pre-converted tf32 bits; layer 0
// fp32 (convert here); k>=189 zero pad.
static __device__ __forceinline__ uint32_t ldx(const float* __restrict__ s0,
                                               const uint32_t* __restrict__ s1,
                                               const uint32_t* __restrict__ s2,
                                               int r, int c, int k)
{
    if (k < 144)      return s2[(4 * r + k / 12) * 72 + 4 * c + (k % 12)];
    else if (k < 180) { int u = k - 144; return s1[(2 * r + u / 6) * 36 + 2 * c + (u % 6)]; }
    else if (k < 189) { int u = k - 180; return f2tf32(s0[(r + u / 3) * 18 + c + (u % 3)]); }
    else              return 0u;
}

// ---------------------------------------------------------------------------
// CTA: batch n, 16x16 position tile (256 positions), K=192, N=64.
// Warp w owns tile rows 2w and 2w+1 (two m16 tiles sharing B fragments).
// ---------------------------------------------------------------------------
__global__ void __launch_bounds__(NT, 2)
sr_mma(const float* __restrict__ gx0, const float* __restrict__ gx1,
       const float* __restrict__ gx2, const float* __restrict__ gw,
       float* __restrict__ out)
{
    extern __shared__ float sm[];
    float*    s_x0 = sm + OFF_P0;
    uint32_t* s_x1 = (uint32_t*)(sm + OFF_P1);
    uint32_t* s_x2 = (uint32_t*)(sm + OFF_P2);

    const int tid  = threadIdx.x;
    const int wid  = tid >> 5;
    const int lane = tid & 31;
    const int n    = blockIdx.z;
    const int i0   = blockIdx.y * 16;
    const int j0   = blockIdx.x * 16;

    // ---- stage patches ----
    {
        const float* src = gx0 + n * 4096;
        for (int idx = tid; idx < 18 * 18; idx += NT) {
            int r = idx / 18, c = idx - r * 18;
            int gi = i0 - 1 + r, gj = j0 - 1 + c;
            float v = 0.0f;
            if ((unsigned)gi < 64u && (unsigned)gj < 64u) v = src[gi * 64 + gj];
            s_x0[idx] = v;
        }
    }
    {
        const float* src = gx1 + n * 16384;
        for (int idx = tid; idx < 36 * 36; idx += NT) {
            int r = idx / 36, c = idx - r * 36;
            int gi = 2 * i0 - 2 + r, gj = 2 * j0 - 2 + c;
            float v = 0.0f;
            if ((unsigned)gi < 128u && (unsigned)gj < 128u) v = src[gi * 128 + gj];
            s_x1[idx] = f2tf32(v);
        }
    }
    {
        const float* src = gx2 + n * 65536;
        for (int idx = tid; idx < 72 * 72; idx += NT) {
            int r = idx / 72, c = idx - r * 72;
            int gi = 4 * i0 - 4 + r, gj = 4 * j0 - 4 + c;
            float v = 0.0f;
            if ((unsigned)gi < 256u && (unsigned)gj < 256u) v = src[gi * 256 + gj];
            s_x2[idx] = f2tf32(v);
        }
    }
    // ---- stage W as sW[n][k] (transpose + K-permute + tf32 round) ----
    {
        uint32_t* sw = (uint32_t*)(sm + OFF_W);
        for (int e = tid; e < 12096; e += NT) {
            int kk = e >> 6, nn = e & 63;
            int k = (kk < 9) ? (180 + kk) : (kk < 45) ? (144 + kk - 9) : (kk - 45);
            sw[nn * XSTR + k] = f2tf32(gw[e]);
        }
        if (tid < 192) {                       // pad taps k=189..191
            int nn = tid & 63, k = 189 + (tid >> 6);
            sw[nn * XSTR + k] = 0u;
        }
    }
    __syncthreads();

    // ---- GEMM: 24 K-steps x 2 m-tiles x 8 n-blocks of m16n8k8 ----
    const int g = lane >> 2, t = lane & 3;
    const int r0 = wid * 2;            // first tile row of this warp
    const uint32_t* Br = (const uint32_t*)(sm + OFF_W) + g * XSTR + t;

    float acc[2][8][4];
#pragma unroll
    for (int mt = 0; mt < 2; ++mt)
#pragma unroll
        for (int nb = 0; nb < 8; ++nb)
#pragma unroll
            for (int q = 0; q < 4; ++q) acc[mt][nb][q] = 0.0f;

#pragma unroll
    for (int s = 0; s < 24; ++s) {
        const int k0 = 8 * s;
        uint32_t a[2][4];
#pragma unroll
        for (int mt = 0; mt < 2; ++mt) {
            const int r = r0 + mt;
            a[mt][0] = ldx(s_x0, s_x1, s_x2, r, g,     k0 + t);
            a[mt][1] = ldx(s_x0, s_x1, s_x2, r, g + 8, k0 + t);
            a[mt][2] = ldx(s_x0, s_x1, s_x2, r, g,     k0 + 4 + t);
            a[mt][3] = ldx(s_x0, s_x1, s_x2, r, g + 8, k0 + 4 + t);
        }
#pragma unroll
        for (int nb = 0; nb < 8; ++nb) {
            uint32_t b0 = Br[nb * 8 * XSTR + k0];
            uint32_t b1 = Br[nb * 8 * XSTR + k0 + 4];
            mma_tf32(acc[0][nb], a[0][0], a[0][1], a[0][2], a[0][3], b0, b1);
            mma_tf32(acc[1][nb], a[1][0], a[1][1], a[1][2], a[1][3], b0, b1);
        }
    }

    // ---- epilogue: 4 positions per thread: (r0+mt, g + 8*rr) ----
#pragma unroll
    for (int mt = 0; mt < 2; ++mt) {
#pragma unroll
        for (int rr = 0; rr < 2; ++rr) {
            float v[16];
#pragma unroll
            for (int nb = 0; nb < 8; ++nb) {
                v[2 * nb]     = fmaxf(acc[mt][nb][rr * 2],     0.0f);
                v[2 * nb + 1] = fmaxf(acc[mt][nb][rr * 2 + 1], 0.0f);
            }
            float m = v[0];
#pragma unroll
            for (int o = 1; o < 16; ++o) m = fmaxf(m, v[o]);
            m = fmaxf(m, __shfl_xor_sync(0xffffffffu, m, 1));
            m = fmaxf(m, __shfl_xor_sync(0xffffffffu, m, 2));
            float ssum = 0.0f;
#pragma unroll
            for (int o = 0; o < 16; ++o) {
                v[o] = __expf(v[o] - m);
                ssum += v[o];
            }
            ssum += __shfl_xor_sync(0xffffffffu, ssum, 1);
            ssum += __shfl_xor_sync(0xffffffffu, ssum, 2);

            const int r = r0 + mt;
            const int c = g + 8 * rr;
            const float xsel  = s_x0[(r + 1) * 18 + (c + 1)];
            const float scale = xsel / ssum;

            const int gi = i0 + r, gj = j0 + c;
            float* base = out + ((size_t)n << 18) + (size_t)(gi * 8) * 512
                              + gj * 8 + 2 * t;
#pragma unroll
            for (int nb = 0; nb < 8; ++nb) {
                float2 o2 = make_float2(scale * v[2 * nb], scale * v[2 * nb + 1]);
                *(float2*)(base + (size_t)nb * 512) = o2;
            }
        }
    }
}

extern "C" void kernel_launch(void* const* d_in, const int* in_sizes, int n_in,
                              void* d_out, int out_size)
{
    const float* x0 = (const float*)d_in[0];
    const float* x1 = (const float*)d_in[1];
    const float* x2 = (const float*)d_in[2];
    const float* w  = (const float*)d_in[3];
    float* out = (float*)d_out;

    const int smem_bytes = NW_TOTAL * (int)sizeof(float);   // 77392 B
    cudaFuncSetAttribute(sr_mma, cudaFuncAttributeMaxDynamicSharedMemorySize,
                         smem_bytes);

    dim3 grid(4, 4, 64);   // 1024 CTAs
    sr_mma<<<grid, NT, smem_bytes>>>(x0, x1, x2, w, out);
}

// round 8
// speedup vs baseline: 8.2678x; 1.4047x over previous
#include <cuda_runtime.h>
#include <cuda_fp16.h>
#include <cstdint>

#define NT 256

// ---- shared-memory word offsets ----
#define OFF_WF    0        // W fragments: 192 groups * 33 = 6336 words
#define OFF_X2P   6336     // x2 packed pairs: 40 rows * 36 = 1440
#define OFF_X1P   7776     // x1 packed pairs: 20 rows * 18 = 360
#define OFF_P0    8136     // x0 pair (x[c],x[c+1]): 10*18 = 180
#define OFF_P0B   8316     // x0 pair (x[c],0):      10*18 = 180
#define OFF_X0F   8496     // x0 fp32 (for xsel):    10*18 = 180
#define SMW_TOTAL 8676     // 34704 bytes

__device__ __align__(16) uint32_t g_wfrag[6336];

// K-step/slot -> original weight row (kk in [0,189)), or -1 = zero pad.
// Must mirror the A-side address scheme in the mainloop exactly.
__host__ __device__ __forceinline__ void tapmap(int s, int reg, int t,
                                                int& lo, int& hi)
{
    if (s < 6)       { int di = reg ? 4 + t : t;                // layer2 rows 0..7
                       lo = 45 + 12 * di + 2 * s; hi = lo + 1; }
    else if (s < 9)  { int m = s - 6; int di = 8 + t;           // layer2 rows 8..11
                       int jj = 2 * m + reg;
                       lo = 45 + 12 * di + 2 * jj; hi = lo + 1; }
    else if (s == 9) { int di = t;                              // layer1 rows 0..3, dj 0..3
                       lo = 9 + 6 * di + 2 * reg; hi = lo + 1; }
    else if (s == 10) {
        if (reg == 0) { lo = 9 + 6 * t + 4; hi = lo + 1; }      // layer1 rows 0..3, dj 4,5
        else { int di = 4 + (t & 1); int jj = t >> 1;           // layer1 rows 4,5, dj 0..3
               lo = 9 + 6 * di + 2 * jj; hi = lo + 1; }
    } else { // s == 11
        if (reg == 0) {
            if (t < 2) { lo = 9 + 6 * (4 + t) + 4; hi = lo + 1; }  // layer1 r4,5 dj4,5
            else       { lo = 3 * (t - 2); hi = lo + 1; }          // layer0 r0,1 dj0,1
        } else {
            if (t == 0) { lo = 6; hi = 7; }                        // layer0 r2 dj0,1
            else        { lo = 3 * (t - 1) + 2; hi = -1; }         // layer0 dj2 (+zero)
        }
    }
}

__global__ void wprep(const float* __restrict__ gw)
{
    int i = blockIdx.x * 256 + threadIdx.x;
    if (i >= 6144) return;
    int G = i >> 5, slot = i & 31;
    int t = slot >> 3, g = slot & 7;
    int s = G >> 4, rem = G & 15, reg = rem >> 3, nb = rem & 7;
    int lo, hi; tapmap(s, reg, t, lo, hi);
    int nn = nb * 8 + g;
    float flo = (lo >= 0) ? gw[lo * 64 + nn] : 0.0f;
    float fhi = (hi >= 0) ? gw[hi * 64 + nn] : 0.0f;
    __half2 h = __floats2half2_rn(flo, fhi);
    g_wfrag[G * 33 + slot] = *reinterpret_cast<uint32_t*>(&h);
    if (slot == 0) g_wfrag[G * 33 + 32] = 0u;   // pad word
}

static __device__ __forceinline__ uint32_t packh2(float lo, float hi)
{
    __half2 h = __floats2half2_rn(lo, hi);
    return *reinterpret_cast<uint32_t*>(&h);
}

static __device__ __forceinline__ void mma_f16(float* c,
                                               uint32_t a0, uint32_t a1,
                                               uint32_t a2, uint32_t a3,
                                               uint32_t b0, uint32_t b1)
{
    asm volatile(
        "mma.sync.aligned.m16n8k16.row.col.f32.f16.f16.f32 "
        "{%0,%1,%2,%3}, {%4,%5,%6,%7}, {%8,%9}, {%0,%1,%2,%3};"
        : "+f"(c[0]), "+f"(c[1]), "+f"(c[2]), "+f"(c[3])
        : "r"(a0), "r"(a1), "r"(a2), "r"(a3), "r"(b0), "r"(b1));
}

// ---------------------------------------------------------------------------
// CTA: batch n, 8x16 tile of positions. Warp w = tile row w (16 positions x 64
// outputs, one m16n8k16 chain of 12 k-steps). MMA M index = tile column.
// ---------------------------------------------------------------------------
__global__ void __launch_bounds__(NT, 4)
sr_f16(const float* __restrict__ gx0, const float* __restrict__ gx1,
       const float* __restrict__ gx2, float* __restrict__ out)
{
    __shared__ uint32_t smw[SMW_TOTAL];

    const int tid  = threadIdx.x;
    const int wid  = tid >> 5;
    const int lane = tid & 31;
    const int n    = blockIdx.z;
    const int i0   = blockIdx.y * 8;
    const int j0   = blockIdx.x * 16;

    // ---- stage W fragments (pure vector copy) ----
    {
        const uint4* src = (const uint4*)g_wfrag;
        uint4* dst = (uint4*)(smw + OFF_WF);
        for (int i = tid; i < 1584; i += NT) dst[i] = src[i];
    }
    // ---- stage x2 as packed half pairs: row 0..39, pair-col 0..35 ----
    {
        const float* src = gx2 + n * 65536;
        for (int i = tid; i < 1440; i += NT) {
            int row = i / 36, pc = i - row * 36;
            int gi = 4 * i0 - 4 + row;
            int gj = 4 * j0 - 4 + 2 * pc;
            float a = 0.0f, b = 0.0f;
            if ((unsigned)gi < 256u) {
                const float* rp = src + gi * 256;
                if ((unsigned)gj < 256u)       a = rp[gj];
                if ((unsigned)(gj + 1) < 256u) b = rp[gj + 1];
            }
            smw[OFF_X2P + i] = packh2(a, b);
        }
    }
    // ---- stage x1 pairs: row 0..19, pair-col 0..17 ----
    {
        const float* src = gx1 + n * 16384;
        for (int i = tid; i < 360; i += NT) {
            int row = i / 18, pc = i - row * 18;
            int gi = 2 * i0 - 2 + row;
            int gj = 2 * j0 - 2 + 2 * pc;
            float a = 0.0f, b = 0.0f;
            if ((unsigned)gi < 128u) {
                const float* rp = src + gi * 128;
                if ((unsigned)gj < 128u)       a = rp[gj];
                if ((unsigned)(gj + 1) < 128u) b = rp[gj + 1];
            }
            smw[OFF_X1P + i] = packh2(a, b);
        }
    }
    // ---- stage x0: fp32 (xsel) + two pair variants ----
    {
        const float* src = gx0 + n * 4096;
        for (int i = tid; i < 180; i += NT) {
            int row = i / 18, col = i - row * 18;
            int gi = i0 - 1 + row, gj = j0 - 1 + col;
            float a = 0.0f, b = 0.0f;
            if ((unsigned)gi < 64u) {
                const float* rp = src + gi * 64;
                if ((unsigned)gj < 64u)       a = rp[gj];
                if ((unsigned)(gj + 1) < 64u) b = rp[gj + 1];
            }
            smw[OFF_X0F + i] = __float_as_uint(a);
            smw[OFF_P0  + i] = packh2(a, b);
            smw[OFF_P0B + i] = packh2(a, 0.0f);
        }
    }
    __syncthreads();

    // ---- per-thread precomputed bases ----
    const int g = lane >> 2, t = lane & 3;
    const int r = wid;                    // tile row for this warp
    const int i2   = OFF_X2P + (4 * r + t) * 36 + 2 * g;
    const int i1   = OFF_X1P + (2 * r + t) * 18 + g;
    const int u1o  = OFF_X1P + 2 * r * 18 + g + 72 + (t & 1) * 18 + (t >> 1);
    const int s11a = (t < 2) ? (OFF_X1P + (2 * r + 4 + t) * 18 + g + 2)
                             : (OFF_P0  + (r + t - 2) * 18 + g);
    const int s11b = (t == 0) ? (OFF_P0  + (r + 2) * 18 + g)
                              : (OFF_P0B + (r + t - 1) * 18 + g + 2);
    const int wfb  = OFF_WF + 8 * t + g;

    float acc[8][4];
#pragma unroll
    for (int nb = 0; nb < 8; ++nb)
#pragma unroll
        for (int q = 0; q < 4; ++q) acc[nb][q] = 0.0f;

#pragma unroll
    for (int s = 0; s < 12; ++s) {
        uint32_t a0, a1, a2, a3;
        if (s < 6) {
            a0 = smw[i2 + s];        a1 = smw[i2 + 16 + s];
            a2 = smw[i2 + 144 + s];  a3 = smw[i2 + 160 + s];
        } else if (s < 9) {
            const int m2 = 2 * (s - 6);
            a0 = smw[i2 + 288 + m2]; a1 = smw[i2 + 304 + m2];
            a2 = smw[i2 + 289 + m2]; a3 = smw[i2 + 305 + m2];
        } else if (s == 9) {
            a0 = smw[i1];     a1 = smw[i1 + 8];
            a2 = smw[i1 + 1]; a3 = smw[i1 + 9];
        } else if (s == 10) {
            a0 = smw[i1 + 2]; a1 = smw[i1 + 10];
            a2 = smw[u1o];    a3 = smw[u1o + 8];
        } else {
            a0 = smw[s11a];   a1 = smw[s11a + 8];
            a2 = smw[s11b];   a3 = smw[s11b + 8];
        }
#pragma unroll
        for (int nb = 0; nb < 8; ++nb) {
            uint32_t b0 = smw[wfb + (s * 16 + nb) * 33];
            uint32_t b1 = smw[wfb + (s * 16 + 8 + nb) * 33];
            mma_f16(acc[nb], a0, a1, a2, a3, b0, b1);
        }
    }

    // ---- epilogue: positions (r, g) and (r, g+8) ----
#pragma unroll
    for (int rr = 0; rr < 2; ++rr) {
        float v[16];
#pragma unroll
        for (int nb = 0; nb < 8; ++nb) {
            v[2 * nb]     = fmaxf(acc[nb][rr * 2],     0.0f);
            v[2 * nb + 1] = fmaxf(acc[nb][rr * 2 + 1], 0.0f);
        }
        float m = v[0];
#pragma unroll
        for (int o = 1; o < 16; ++o) m = fmaxf(m, v[o]);
        m = fmaxf(m, __shfl_xor_sync(0xffffffffu, m, 1));
        m = fmaxf(m, __shfl_xor_sync(0xffffffffu, m, 2));
        float ssum = 0.0f;
#pragma unroll
        for (int o = 0; o < 16; ++o) {
            v[o] = __expf(v[o] - m);
            ssum += v[o];
        }
        ssum += __shfl_xor_sync(0xffffffffu, ssum, 1);
        ssum += __shfl_xor_sync(0xffffffffu, ssum, 2);

        const int c = g + 8 * rr;
        const float xsel  = __uint_as_float(smw[OFF_X0F + (r + 1) * 18 + (c + 1)]);
        const float scale = xsel / ssum;

        const int gi = i0 + r, gj = j0 + c;
        float* base = out + ((size_t)n << 18) + (size_t)(gi * 8) * 512
                          + gj * 8 + 2 * t;
#pragma unroll
        for (int nb = 0; nb < 8; ++nb) {
            float2 o2 = make_float2(scale * v[2 * nb], scale * v[2 * nb + 1]);
            *(float2*)(base + (size_t)nb * 512) = o2;
        }
    }
}

extern "C" void kernel_launch(void* const* d_in, const int* in_sizes, int n_in,
                              void* d_out, int out_size)
{
    const float* x0 = (const float*)d_in[0];
    const float* x1 = (const float*)d_in[1];
    const float* x2 = (const float*)d_in[2];
    const float* w  = (const float*)d_in[3];
    float* out = (float*)d_out;

    wprep<<<24, 256>>>(w);
    dim3 grid(4, 8, 64);   // (j-tiles, i-tiles, batch) -> 2048 CTAs
    sr_f16<<<grid, NT>>>(x0, x1, x2, out);
}